// round 2
// baseline (speedup 1.0000x reference)
#include <cuda_runtime.h>
#include <cstdint>

// LSTMModelClassify: B=2048, T=512, D=1, H=50, C=2, 2-layer LSTM + FC.
// Persistent-block design: 147 blocks (1 wave), each owns NB=14 batch elems,
// iterates all 512 timesteps through both layers. Weights + x-slice + state in smem.
// Gate GEMVs use fma.rn.f32x2 (FFMA2) with k-packed operands from LDS.128.

#define TPB 128
constexpr int NB    = 14;    // batch elems per block
constexpr int Hh    = 50;
constexpr int G4    = 200;   // 4*H
constexpr int Tt    = 512;
constexpr int BATCH = 2048;
constexpr int NC    = 2;
constexpr int W0S   = 52;    // Whh0 row stride (50 + 2 pad, 16B-aligned, conflict-free)
constexpr int W1S   = 108;   // [Wih1 | pad | Whh1 | pad] row stride
constexpr int GBS   = 17;    // gate-buffer stride (odd -> conflict-free)

// shared memory layout (floats)
constexpr int OFF_W0   = 0;
constexpr int OFF_W1   = OFF_W0   + G4 * W0S;   // 10400
constexpr int OFF_XS   = OFF_W1   + G4 * W1S;   // +21600
constexpr int OFF_BUFA = OFF_XS   + NB * Tt;    // +7168   h1 state [b][52]
constexpr int OFF_BUFB = OFF_BUFA + NB * W0S;   // +728    h2 state [b][52]
constexpr int OFF_GBUF = OFF_BUFB + NB * W0S;   // +728    raw gates [200][17]
constexpr int OFF_B0   = OFF_GBUF + G4 * GBS;   // +3400
constexpr int OFF_B1   = OFF_B0   + G4;
constexpr int OFF_WX   = OFF_B1   + G4;
constexpr int OFF_WFC  = OFF_WX   + G4;
constexpr int OFF_BFC  = OFF_WFC  + NC * Hh;
constexpr int SMEMF    = OFF_BFC  + NC;         // total floats (~44.7K -> ~175KB)

__device__ __forceinline__ unsigned long long ffma2(unsigned long long a,
                                                    unsigned long long b,
                                                    unsigned long long c) {
    unsigned long long d;
    asm("fma.rn.f32x2 %0, %1, %2, %3;" : "=l"(d) : "l"(a), "l"(b), "l"(c));
    return d;
}

__device__ __forceinline__ void unpack2(unsigned long long a, float& x, float& y) {
    unsigned lo, hi;
    asm("mov.b64 {%0, %1}, %2;" : "=r"(lo), "=r"(hi) : "l"(a));
    x = __uint_as_float(lo);
    y = __uint_as_float(hi);
}

__device__ __forceinline__ float sigf(float x) {
    float e = __expf(-x);
    return __fdividef(1.0f, 1.0f + e);
}
__device__ __forceinline__ float tanh_(float x) {
    float e = __expf(2.0f * x);
    return 1.0f - __fdividef(2.0f, 1.0f + e);
}

// K-packed MAC loop: 2 gates x NB batch, 4 k per iteration.
// Weight .128 load yields two f32x2 k-pairs; h .128 load likewise. No pack MOVs.
__device__ __forceinline__ void mac_loop(const float* __restrict__ w0p,
                                         const float* __restrict__ w1p,
                                         const float* __restrict__ buf,
                                         unsigned long long (&a0)[NB],
                                         unsigned long long (&a1)[NB]) {
#pragma unroll 2
    for (int k4 = 0; k4 < 13; ++k4) {
        ulonglong2 wv0 = *reinterpret_cast<const ulonglong2*>(w0p + 4 * k4);
        ulonglong2 wv1 = *reinterpret_cast<const ulonglong2*>(w1p + 4 * k4);
#pragma unroll
        for (int b = 0; b < NB; ++b) {
            ulonglong2 hv = *reinterpret_cast<const ulonglong2*>(buf + b * W0S + 4 * k4);
            a0[b] = ffma2(hv.x, wv0.x, a0[b]);
            a0[b] = ffma2(hv.y, wv0.y, a0[b]);
            a1[b] = ffma2(hv.x, wv1.x, a1[b]);
            a1[b] = ffma2(hv.y, wv1.y, a1[b]);
        }
    }
}

__global__ void __launch_bounds__(TPB, 1) lstm_kernel(
    const float* __restrict__ x,
    const float* __restrict__ Wih0, const float* __restrict__ Whh0,
    const float* __restrict__ bih0, const float* __restrict__ bhh0,
    const float* __restrict__ Wih1, const float* __restrict__ Whh1,
    const float* __restrict__ bih1, const float* __restrict__ bhh1,
    const float* __restrict__ Wfc,  const float* __restrict__ bfc,
    float* __restrict__ out)
{
    extern __shared__ __align__(16) float sm[];
    const int tid = threadIdx.x;
    const int b0  = blockIdx.x * NB;

    // zero all smem (also provides zero pads + zero initial h states)
    for (int i = tid; i < SMEMF; i += TPB) sm[i] = 0.0f;
    __syncthreads();

    float* W0   = sm + OFF_W0;
    float* W1   = sm + OFF_W1;
    float* xs   = sm + OFF_XS;
    float* bufA = sm + OFF_BUFA;
    float* bufB = sm + OFF_BUFB;
    float* gbuf = sm + OFF_GBUF;
    float* bs0  = sm + OFF_B0;
    float* bs1  = sm + OFF_B1;
    float* wx0  = sm + OFF_WX;
    float* wfc  = sm + OFF_WFC;
    float* bfcs = sm + OFF_BFC;

    // stage weights
    for (int i = tid; i < G4 * Hh; i += TPB) {
        int g = i / Hh, k = i % Hh;
        W0[g * W0S + k]      = Whh0[i];
        W1[g * W1S + k]      = Wih1[i];
        W1[g * W1S + 52 + k] = Whh1[i];
    }
    for (int i = tid; i < G4; i += TPB) {
        bs0[i] = bih0[i] + bhh0[i];
        bs1[i] = bih1[i] + bhh1[i];
        wx0[i] = Wih0[i];          // D=1: column vector
    }
    // stage x slice: xs[b][t]
    for (int i = tid; i < NB * Tt; i += TPB) {
        int b = i / Tt, t = i % Tt;
        int gb = b0 + b;
        xs[i] = (gb < BATCH) ? x[gb * Tt + t] : 0.0f;
    }
    for (int i = tid; i < NC * Hh; i += TPB) wfc[i] = Wfc[i];
    if (tid < NC) bfcs[tid] = bfc[tid];
    __syncthreads();

    // gate-thread role: 4 warps x 25 lanes x 2 gates = 200 gates
    const int  lane = tid & 31;
    const int  warp = tid >> 5;
    const bool gact = lane < 25;
    const int  g0 = warp * 50 + lane;
    const int  g1 = g0 + 25;
    float bg0 = 0.f, bg1 = 0.f, b2g0 = 0.f, b2g1 = 0.f, wxg0 = 0.f, wxg1 = 0.f;
    if (gact) {
        bg0 = bs0[g0]; bg1 = bs0[g1];
        b2g0 = bs1[g0]; b2g1 = bs1[g1];
        wxg0 = wx0[g0]; wxg1 = wx0[g1];
    }

    // elementwise role: 700 (j,b) cells per layer across 128 threads
    int  ej[6], eb[6];
    bool eok[6];
    float c1s[6], c2s[6];
#pragma unroll
    for (int i = 0; i < 6; ++i) {
        int u = tid + TPB * i;
        eok[i] = (u < Hh * NB);
        eb[i] = u / Hh;
        ej[i] = u % Hh;
        c1s[i] = 0.f; c2s[i] = 0.f;
    }

    for (int t = 0; t < Tt; ++t) {
        // ---- Layer 1 gates: g = bias + Wih0*x_t + Whh0 @ h1 ----
        if (gact) {
            unsigned long long a0[NB], a1[NB];
#pragma unroll
            for (int b = 0; b < NB; ++b) { a0[b] = 0ULL; a1[b] = 0ULL; }
            mac_loop(W0 + g0 * W0S, W0 + g1 * W0S, bufA, a0, a1);
#pragma unroll
            for (int b = 0; b < NB; ++b) {
                float xv = xs[b * Tt + t];
                float lo, hi;
                unpack2(a0[b], lo, hi);
                gbuf[g0 * GBS + b] = lo + hi + fmaf(wxg0, xv, bg0);
                unpack2(a1[b], lo, hi);
                gbuf[g1 * GBS + b] = lo + hi + fmaf(wxg1, xv, bg1);
            }
        }
        __syncthreads();

        // ---- Layer 1 elementwise: c1, h1 ----
#pragma unroll
        for (int i = 0; i < 6; ++i) if (eok[i]) {
            int j = ej[i], b = eb[i];
            float gi = gbuf[j * GBS + b];
            float gf = gbuf[(j + 50) * GBS + b];
            float gg = gbuf[(j + 100) * GBS + b];
            float go = gbuf[(j + 150) * GBS + b];
            float cc = sigf(gf) * c1s[i] + sigf(gi) * tanh_(gg);
            c1s[i] = cc;
            bufA[b * W0S + j] = sigf(go) * tanh_(cc);
        }
        __syncthreads();

        // ---- Layer 2 gates: g = bias + Wih1 @ h1_t + Whh1 @ h2_{t-1} ----
        if (gact) {
            unsigned long long a0[NB], a1[NB];
#pragma unroll
            for (int b = 0; b < NB; ++b) { a0[b] = 0ULL; a1[b] = 0ULL; }
            mac_loop(W1 + g0 * W1S,      W1 + g1 * W1S,      bufA, a0, a1);
            mac_loop(W1 + g0 * W1S + 52, W1 + g1 * W1S + 52, bufB, a0, a1);
#pragma unroll
            for (int b = 0; b < NB; ++b) {
                float lo, hi;
                unpack2(a0[b], lo, hi);
                gbuf[g0 * GBS + b] = lo + hi + b2g0;
                unpack2(a1[b], lo, hi);
                gbuf[g1 * GBS + b] = lo + hi + b2g1;
            }
        }
        __syncthreads();

        // ---- Layer 2 elementwise: c2, h2 ----
#pragma unroll
        for (int i = 0; i < 6; ++i) if (eok[i]) {
            int j = ej[i], b = eb[i];
            float gi = gbuf[j * GBS + b];
            float gf = gbuf[(j + 50) * GBS + b];
            float gg = gbuf[(j + 100) * GBS + b];
            float go = gbuf[(j + 150) * GBS + b];
            float cc = sigf(gf) * c2s[i] + sigf(gi) * tanh_(gg);
            c2s[i] = cc;
            bufB[b * W0S + j] = sigf(go) * tanh_(cc);
        }
        __syncthreads();
    }

    // ---- Final FC on last h2 ----
    if (tid < NB * NC) {
        int bl = tid >> 1;
        int c  = tid & 1;
        int gb = b0 + bl;
        if (gb < BATCH) {
            float s = bfcs[c];
#pragma unroll
            for (int j = 0; j < Hh; ++j) s += wfc[c * Hh + j] * bufB[bl * W0S + j];
            out[gb * NC + c] = s;
        }
    }
}

extern "C" void kernel_launch(void* const* d_in, const int* in_sizes, int n_in,
                              void* d_out, int out_size) {
    const float* x    = (const float*)d_in[0];
    const float* Wih0 = (const float*)d_in[1];
    const float* Whh0 = (const float*)d_in[2];
    const float* bih0 = (const float*)d_in[3];
    const float* bhh0 = (const float*)d_in[4];
    const float* Wih1 = (const float*)d_in[5];
    const float* Whh1 = (const float*)d_in[6];
    const float* bih1 = (const float*)d_in[7];
    const float* bhh1 = (const float*)d_in[8];
    const float* Wfc  = (const float*)d_in[9];
    const float* bfc  = (const float*)d_in[10];
    float* out = (float*)d_out;

    const int smem_bytes = SMEMF * (int)sizeof(float);
    cudaFuncSetAttribute(lstm_kernel, cudaFuncAttributeMaxDynamicSharedMemorySize, smem_bytes);

    const int grid = (BATCH + NB - 1) / NB;   // 147 blocks, one wave
    lstm_kernel<<<grid, TPB, smem_bytes>>>(x, Wih0, Whh0, bih0, bhh0,
                                           Wih1, Whh1, bih1, bhh1,
                                           Wfc, bfc, out);
}

// round 3
// speedup vs baseline: 1.1836x; 1.1836x over previous
#include <cuda_runtime.h>
#include <cstdint>

// LSTMModelClassify: B=2048, T=512, D=1, H=50, C=2, 2-layer LSTM + FC.
// Persistent-block design: 147 blocks (1 wave), each owns NB=14 batch elems.
// R2: TPB=256 (2 warps/SMSP). Warp w handles gate-quarter (w&3), batch-half (w>>2).
// Gate GEMVs use fma.rn.f32x2 (FFMA2) with k-packed operands from LDS.128.

#define TPB 256
constexpr int NB    = 14;    // batch elems per block
constexpr int BH    = 7;     // batch per warp (half)
constexpr int Hh    = 50;
constexpr int G4    = 200;   // 4*H
constexpr int Tt    = 512;
constexpr int BATCH = 2048;
constexpr int NC    = 2;
constexpr int W0S   = 52;    // Whh0 row stride (50 + 2 pad, 16B-aligned, conflict-free)
constexpr int W1S   = 108;   // [Wih1 | pad | Whh1 | pad] row stride
constexpr int GBS   = 17;    // gate-buffer stride (odd -> conflict-free)

// shared memory layout (floats)
constexpr int OFF_W0   = 0;
constexpr int OFF_W1   = OFF_W0   + G4 * W0S;
constexpr int OFF_XS   = OFF_W1   + G4 * W1S;
constexpr int OFF_BUFA = OFF_XS   + NB * Tt;    // h1 state [b][52]
constexpr int OFF_BUFB = OFF_BUFA + NB * W0S;   // h2 state [b][52]
constexpr int OFF_GBUF = OFF_BUFB + NB * W0S;   // raw gates [200][17]
constexpr int OFF_B0   = OFF_GBUF + G4 * GBS;
constexpr int OFF_B1   = OFF_B0   + G4;
constexpr int OFF_WX   = OFF_B1   + G4;
constexpr int OFF_WFC  = OFF_WX   + G4;
constexpr int OFF_BFC  = OFF_WFC  + NC * Hh;
constexpr int SMEMF    = OFF_BFC  + NC;

__device__ __forceinline__ unsigned long long ffma2(unsigned long long a,
                                                    unsigned long long b,
                                                    unsigned long long c) {
    unsigned long long d;
    asm("fma.rn.f32x2 %0, %1, %2, %3;" : "=l"(d) : "l"(a), "l"(b), "l"(c));
    return d;
}

__device__ __forceinline__ void unpack2(unsigned long long a, float& x, float& y) {
    unsigned lo, hi;
    asm("mov.b64 {%0, %1}, %2;" : "=r"(lo), "=r"(hi) : "l"(a));
    x = __uint_as_float(lo);
    y = __uint_as_float(hi);
}

__device__ __forceinline__ float sigf(float x) {
    float e = __expf(-x);
    return __fdividef(1.0f, 1.0f + e);
}
__device__ __forceinline__ float tanh_(float x) {
    float e = __expf(2.0f * x);
    return 1.0f - __fdividef(2.0f, 1.0f + e);
}

// K-packed MAC loop: 2 gates x BH batch, 4 k per iteration.
// Weight .128 load yields two f32x2 k-pairs; h .128 load likewise.
__device__ __forceinline__ void mac_loop(const float* __restrict__ w0p,
                                         const float* __restrict__ w1p,
                                         const float* __restrict__ buf,
                                         unsigned long long (&a0)[BH],
                                         unsigned long long (&a1)[BH]) {
#pragma unroll 2
    for (int k4 = 0; k4 < 13; ++k4) {
        ulonglong2 wv0 = *reinterpret_cast<const ulonglong2*>(w0p + 4 * k4);
        ulonglong2 wv1 = *reinterpret_cast<const ulonglong2*>(w1p + 4 * k4);
#pragma unroll
        for (int b = 0; b < BH; ++b) {
            ulonglong2 hv = *reinterpret_cast<const ulonglong2*>(buf + b * W0S + 4 * k4);
            a0[b] = ffma2(hv.x, wv0.x, a0[b]);
            a0[b] = ffma2(hv.y, wv0.y, a0[b]);
            a1[b] = ffma2(hv.x, wv1.x, a1[b]);
            a1[b] = ffma2(hv.y, wv1.y, a1[b]);
        }
    }
}

__global__ void __launch_bounds__(TPB, 1) lstm_kernel(
    const float* __restrict__ x,
    const float* __restrict__ Wih0, const float* __restrict__ Whh0,
    const float* __restrict__ bih0, const float* __restrict__ bhh0,
    const float* __restrict__ Wih1, const float* __restrict__ Whh1,
    const float* __restrict__ bih1, const float* __restrict__ bhh1,
    const float* __restrict__ Wfc,  const float* __restrict__ bfc,
    float* __restrict__ out)
{
    extern __shared__ __align__(16) float sm[];
    const int tid = threadIdx.x;
    const int b0  = blockIdx.x * NB;

    // zero all smem (also provides zero pads + zero initial h states)
    for (int i = tid; i < SMEMF; i += TPB) sm[i] = 0.0f;
    __syncthreads();

    float* W0   = sm + OFF_W0;
    float* W1   = sm + OFF_W1;
    float* xs   = sm + OFF_XS;
    float* bufA = sm + OFF_BUFA;
    float* bufB = sm + OFF_BUFB;
    float* gbuf = sm + OFF_GBUF;
    float* bs0  = sm + OFF_B0;
    float* bs1  = sm + OFF_B1;
    float* wx0  = sm + OFF_WX;
    float* wfc  = sm + OFF_WFC;
    float* bfcs = sm + OFF_BFC;

    // stage weights
    for (int i = tid; i < G4 * Hh; i += TPB) {
        int g = i / Hh, k = i % Hh;
        W0[g * W0S + k]      = Whh0[i];
        W1[g * W1S + k]      = Wih1[i];
        W1[g * W1S + 52 + k] = Whh1[i];
    }
    for (int i = tid; i < G4; i += TPB) {
        bs0[i] = bih0[i] + bhh0[i];
        bs1[i] = bih1[i] + bhh1[i];
        wx0[i] = Wih0[i];          // D=1: column vector
    }
    // stage x slice: xs[b][t]
    for (int i = tid; i < NB * Tt; i += TPB) {
        int b = i / Tt, t = i % Tt;
        int gb = b0 + b;
        xs[i] = (gb < BATCH) ? x[gb * Tt + t] : 0.0f;
    }
    for (int i = tid; i < NC * Hh; i += TPB) wfc[i] = Wfc[i];
    if (tid < NC) bfcs[tid] = bfc[tid];
    __syncthreads();

    // gate-thread role: 8 warps. warp w: gate-quarter (w&3), batch-half (w>>2).
    // 25 active lanes x 2 gates = 50 gates per quarter; 7 batches per half.
    const int  lane = tid & 31;
    const int  warp = tid >> 5;
    const bool gact = lane < 25;
    const int  gq   = warp & 3;
    const int  hb   = warp >> 2;          // 0 or 1
    const int  bbase = hb * BH;           // batch offset 0 or 7
    const int  g0 = gq * 50 + lane;
    const int  g1 = g0 + 25;
    float bg0 = 0.f, bg1 = 0.f, b2g0 = 0.f, b2g1 = 0.f, wxg0 = 0.f, wxg1 = 0.f;
    if (gact) {
        bg0 = bs0[g0]; bg1 = bs0[g1];
        b2g0 = bs1[g0]; b2g1 = bs1[g1];
        wxg0 = wx0[g0]; wxg1 = wx0[g1];
    }
    float* gb0 = gbuf + g0 * GBS + bbase;
    float* gb1 = gbuf + g1 * GBS + bbase;
    const float* bufAh = bufA + bbase * W0S;
    const float* bufBh = bufB + bbase * W0S;
    const float* xsh   = xs + bbase * Tt;

    // elementwise role: 700 (j,b) cells per layer across 256 threads (3 each max)
    int  ej[3], eb[3];
    bool eok[3];
    float c1s[3], c2s[3];
#pragma unroll
    for (int i = 0; i < 3; ++i) {
        int u = tid + TPB * i;
        eok[i] = (u < Hh * NB);
        eb[i] = u / Hh;
        ej[i] = u % Hh;
        c1s[i] = 0.f; c2s[i] = 0.f;
    }

    for (int t = 0; t < Tt; ++t) {
        // ---- Layer 1 gates: g = bias + Wih0*x_t + Whh0 @ h1 ----
        if (gact) {
            unsigned long long a0[BH], a1[BH];
#pragma unroll
            for (int b = 0; b < BH; ++b) { a0[b] = 0ULL; a1[b] = 0ULL; }
            mac_loop(W0 + g0 * W0S, W0 + g1 * W0S, bufAh, a0, a1);
#pragma unroll
            for (int b = 0; b < BH; ++b) {
                float xv = xsh[b * Tt + t];
                float lo, hi;
                unpack2(a0[b], lo, hi);
                gb0[b] = lo + hi + fmaf(wxg0, xv, bg0);
                unpack2(a1[b], lo, hi);
                gb1[b] = lo + hi + fmaf(wxg1, xv, bg1);
            }
        }
        __syncthreads();

        // ---- Layer 1 elementwise: c1, h1 ----
#pragma unroll
        for (int i = 0; i < 3; ++i) if (eok[i]) {
            int j = ej[i], b = eb[i];
            float gi = gbuf[j * GBS + b];
            float gf = gbuf[(j + 50) * GBS + b];
            float gg = gbuf[(j + 100) * GBS + b];
            float go = gbuf[(j + 150) * GBS + b];
            float cc = sigf(gf) * c1s[i] + sigf(gi) * tanh_(gg);
            c1s[i] = cc;
            bufA[b * W0S + j] = sigf(go) * tanh_(cc);
        }
        __syncthreads();

        // ---- Layer 2 gates: g = bias + Wih1 @ h1_t + Whh1 @ h2_{t-1} ----
        if (gact) {
            unsigned long long a0[BH], a1[BH];
#pragma unroll
            for (int b = 0; b < BH; ++b) { a0[b] = 0ULL; a1[b] = 0ULL; }
            mac_loop(W1 + g0 * W1S,      W1 + g1 * W1S,      bufAh, a0, a1);
            mac_loop(W1 + g0 * W1S + 52, W1 + g1 * W1S + 52, bufBh, a0, a1);
#pragma unroll
            for (int b = 0; b < BH; ++b) {
                float lo, hi;
                unpack2(a0[b], lo, hi);
                gb0[b] = lo + hi + b2g0;
                unpack2(a1[b], lo, hi);
                gb1[b] = lo + hi + b2g1;
            }
        }
        __syncthreads();

        // ---- Layer 2 elementwise: c2, h2 ----
#pragma unroll
        for (int i = 0; i < 3; ++i) if (eok[i]) {
            int j = ej[i], b = eb[i];
            float gi = gbuf[j * GBS + b];
            float gf = gbuf[(j + 50) * GBS + b];
            float gg = gbuf[(j + 100) * GBS + b];
            float go = gbuf[(j + 150) * GBS + b];
            float cc = sigf(gf) * c2s[i] + sigf(gi) * tanh_(gg);
            c2s[i] = cc;
            bufB[b * W0S + j] = sigf(go) * tanh_(cc);
        }
        __syncthreads();
    }

    // ---- Final FC on last h2 ----
    if (tid < NB * NC) {
        int bl = tid >> 1;
        int c  = tid & 1;
        int gb = b0 + bl;
        if (gb < BATCH) {
            float s = bfcs[c];
#pragma unroll
            for (int j = 0; j < Hh; ++j) s += wfc[c * Hh + j] * bufB[bl * W0S + j];
            out[gb * NC + c] = s;
        }
    }
}

extern "C" void kernel_launch(void* const* d_in, const int* in_sizes, int n_in,
                              void* d_out, int out_size) {
    const float* x    = (const float*)d_in[0];
    const float* Wih0 = (const float*)d_in[1];
    const float* Whh0 = (const float*)d_in[2];
    const float* bih0 = (const float*)d_in[3];
    const float* bhh0 = (const float*)d_in[4];
    const float* Wih1 = (const float*)d_in[5];
    const float* Whh1 = (const float*)d_in[6];
    const float* bih1 = (const float*)d_in[7];
    const float* bhh1 = (const float*)d_in[8];
    const float* Wfc  = (const float*)d_in[9];
    const float* bfc  = (const float*)d_in[10];
    float* out = (float*)d_out;

    const int smem_bytes = SMEMF * (int)sizeof(float);
    cudaFuncSetAttribute(lstm_kernel, cudaFuncAttributeMaxDynamicSharedMemorySize, smem_bytes);

    const int grid = (BATCH + NB - 1) / NB;   // 147 blocks, one wave
    lstm_kernel<<<grid, TPB, smem_bytes>>>(x, Wih0, Whh0, bih0, bhh0,
                                           Wih1, Whh1, bih1, bhh1,
                                           Wfc, bfc, out);
}